// round 1
// baseline (speedup 1.0000x reference)
#include <cuda_runtime.h>
#include <math.h>

#define T_DIM 512
#define B_DIM 32
#define C1    512
#define H_DIM 512
#define M_DIM 2048   // 4 gates * H

// Scratch (module-load allocated, allowed): raw gate preacts per dir, layer-1 output
__device__ float g_gates[2ull * B_DIM * T_DIM * M_DIM];          // [dir][b][t][m]  (268 MB)
__device__ float g_h1[(size_t)B_DIM * T_DIM * 2 * H_DIM];        // [b][t][2H]      (67 MB)

// ---------------------------------------------------------------------------
// Fused conv-as-GEMM: G[dir][b][t][m] = bias[m] + sum_c sum_kk W[m,c,kk] * Xin(c, torig(t,kk))
//   Xin(c,b,t) = X[t*t_stride + b*b_stride + c]
//   dir==0: torig = t-1+kk ; dir==1 (time-reversed input, kept reversed): torig = T - t - kk
// ---------------------------------------------------------------------------
__global__ __launch_bounds__(256, 2)
void qrnn_gemm(const float* __restrict__ X, const float* __restrict__ W,
               const float* __restrict__ bias, float* __restrict__ G,
               int CIN, int t_stride, int b_stride)
{
    const int bcol = blockIdx.x;           // 0..127 : column tile
    const int b    = bcol >> 2;
    const int t0   = (bcol & 3) * 128;
    const int m0   = blockIdx.y * 128;
    const int dir  = blockIdx.z;

    const float* Wd = W    + (size_t)dir * 4 * H_DIM * CIN * 2;
    const float* bd = bias + (size_t)dir * M_DIM;
    float*       Gd = G    + (size_t)dir * B_DIM * T_DIM * M_DIM;

    __shared__ float As[32][132];          // [k'][m], k' = c_local*2 + kk
    __shared__ float Bs[2][16][132];       // [kk][c_local][t_local]

    const int tid = threadIdx.x;
    const int ty  = tid >> 4;              // 0..15 -> m groups
    const int tx  = tid & 15;              // 0..15 -> t groups

    float acc[8][8];
    #pragma unroll
    for (int i = 0; i < 8; i++)
        #pragma unroll
        for (int j = 0; j < 8; j++) acc[i][j] = 0.f;

    for (int c0 = 0; c0 < CIN; c0 += 16) {
        // --- load A tile: 128 m x 32 k' (global reads 128B-coalesced along k')
        #pragma unroll
        for (int r = 0; r < 16; r++) {
            int idx = r * 256 + tid;       // 0..4095
            int kp  = idx & 31;
            int m   = idx >> 5;
            As[kp][m] = Wd[(size_t)(m0 + m) * CIN * 2 + c0 * 2 + kp];
        }
        // --- load B window: 16 c x 129 time points, duplicated into two kk slices
        for (int idx = tid; idx < 16 * 129; idx += 256) {
            int c = idx & 15;
            int p = idx >> 4;              // 0..128
            int o = (dir == 0) ? (t0 - 1 + p) : (T_DIM - t0 - p);
            float v = 0.f;
            if (o >= 0 && o < T_DIM)
                v = X[(size_t)o * t_stride + (size_t)b * b_stride + (c0 + c)];
            if (p < 128) Bs[0][c][p]     = v;
            if (p >= 1)  Bs[1][c][p - 1] = v;
        }
        __syncthreads();

        // --- 32 k'-steps, split 8x8 micro-tile (conflict-free float4 LDS)
        #pragma unroll
        for (int c = 0; c < 16; c++) {
            #pragma unroll
            for (int kk = 0; kk < 2; kk++) {
                const int kp = c * 2 + kk;
                float a[8], bb[8];
                float4 va0 = *(const float4*)&As[kp][ty * 4];
                float4 va1 = *(const float4*)&As[kp][64 + ty * 4];
                a[0]=va0.x; a[1]=va0.y; a[2]=va0.z; a[3]=va0.w;
                a[4]=va1.x; a[5]=va1.y; a[6]=va1.z; a[7]=va1.w;
                float4 vb0 = *(const float4*)&Bs[kk][c][tx * 4];
                float4 vb1 = *(const float4*)&Bs[kk][c][64 + tx * 4];
                bb[0]=vb0.x; bb[1]=vb0.y; bb[2]=vb0.z; bb[3]=vb0.w;
                bb[4]=vb1.x; bb[5]=vb1.y; bb[6]=vb1.z; bb[7]=vb1.w;
                #pragma unroll
                for (int i = 0; i < 8; i++)
                    #pragma unroll
                    for (int j = 0; j < 8; j++)
                        acc[i][j] = fmaf(a[i], bb[j], acc[i][j]);
            }
        }
        __syncthreads();
    }

    // --- epilogue: add bias, store to G[b][t][m] (32B-aligned float4 stores)
    float bv[8];
    #pragma unroll
    for (int i = 0; i < 4; i++) {
        bv[i]     = bd[m0 + ty * 4 + i];
        bv[i + 4] = bd[m0 + 64 + ty * 4 + i];
    }
    #pragma unroll
    for (int j = 0; j < 8; j++) {
        int tl = (j < 4) ? (tx * 4 + j) : (64 + tx * 4 + (j - 4));
        int t  = t0 + tl;
        size_t base = ((size_t)b * T_DIM + t) * (size_t)M_DIM + m0;
        float4 v0 = make_float4(acc[0][j] + bv[0], acc[1][j] + bv[1],
                                acc[2][j] + bv[2], acc[3][j] + bv[3]);
        float4 v1 = make_float4(acc[4][j] + bv[4], acc[5][j] + bv[5],
                                acc[6][j] + bv[6], acc[7][j] + bv[7]);
        *(float4*)&Gd[base + ty * 4]      = v0;
        *(float4*)&Gd[base + 64 + ty * 4] = v1;
    }
}

// ---------------------------------------------------------------------------
// Activation + recurrence scan. Lanes = (dir, b, h). Coalesced over h.
//   seq_mode 0: write h1[(b*T + t)*1024 + dir*512 + h]         (layer-1 output)
//   seq_mode 1: write out[(t*B + b)*1024 + dir*512 + h]        (final output layout)
//   h_n: dir==0 at t==T-2 ; dir==1 at stored t==0 (matches reference exactly)
// ---------------------------------------------------------------------------
__global__ void qrnn_scan(const float* __restrict__ G, float* __restrict__ seq,
                          float* __restrict__ hn, int seq_mode)
{
    const int h   = blockIdx.x * 256 + threadIdx.x;   // 0..511
    const int b   = blockIdx.y;
    const int dir = blockIdx.z;

    const float* Gd = G + ((size_t)dir * B_DIM * T_DIM + (size_t)b * T_DIM) * M_DIM + h;

    float c = 0.f;
    for (int t = 0; t < T_DIM; t++) {
        const float* p = Gd + (size_t)t * M_DIM;
        float z = tanhf(p[0]);
        float f = 1.f / (1.f + __expf(-p[512]));
        float o = 1.f / (1.f + __expf(-p[1024]));
        float i = 1.f / (1.f + __expf(-p[1536]));
        c = fmaf(f, c, i * z);
        float val = o * c;
        size_t oidx = (seq_mode == 0)
            ? ((size_t)(b * T_DIM + t) * 1024 + dir * 512 + h)
            : ((size_t)(t * B_DIM + b) * 1024 + dir * 512 + h);
        seq[oidx] = val;
        if ((dir == 0 && t == T_DIM - 2) || (dir == 1 && t == 0))
            hn[(size_t)b * 1024 + dir * 512 + h] = val;
    }
}

// ---------------------------------------------------------------------------
extern "C" void kernel_launch(void* const* d_in, const int* in_sizes, int n_in,
                              void* d_out, int out_size)
{
    const float* x  = (const float*)d_in[0];   // (T, B, C)
    const float* w0 = (const float*)d_in[1];   // (2, 4, H, C, 2)
    const float* b0 = (const float*)d_in[2];   // (2, 4, H)
    const float* w1 = (const float*)d_in[3];   // (2, 4, H, 2H, 2)
    const float* b1 = (const float*)d_in[4];   // (2, 4, H)
    float* out = (float*)d_out;                // (T,B,2H) ++ (2,B,2H)

    float *gates, *h1;
    cudaGetSymbolAddress((void**)&gates, g_gates);
    cudaGetSymbolAddress((void**)&h1,    g_h1);

    const size_t OUT_SEQ = (size_t)T_DIM * B_DIM * 2 * H_DIM;   // 16,777,216
    const size_t HN_L    = (size_t)B_DIM * 2 * H_DIM;           // 32,768

    dim3 ggrid(128, 16, 2), gblk(256);
    dim3 sgrid(2, B_DIM, 2), sblk(256);

    // Layer 1: x (T,B,C): t_stride = B*C, b_stride = C
    qrnn_gemm<<<ggrid, gblk>>>(x, w0, b0, gates, C1, B_DIM * C1, C1);
    qrnn_scan<<<sgrid, sblk>>>(gates, h1, out + OUT_SEQ + 0 * HN_L, 0);

    // Layer 2: h1 (B,T,2H): t_stride = 2H, b_stride = T*2H
    qrnn_gemm<<<ggrid, gblk>>>(h1, w1, b1, gates, 2 * H_DIM, 2 * H_DIM, T_DIM * 2 * H_DIM);
    qrnn_scan<<<sgrid, sblk>>>(gates, out, out + OUT_SEQ + 1 * HN_L, 1);
}

// round 3
// speedup vs baseline: 5.0502x; 5.0502x over previous
#include <cuda_runtime.h>
#include <cstdint>
#include <math.h>

#define T_DIM 512
#define B_DIM 32
#define C1    512
#define H_DIM 512
#define M_DIM 2048          // 4 gates * H per direction
#define BC    (B_DIM * C1)  // 16384

// ---------------------------------------------------------------------------
// Scratch (__device__ globals — no runtime allocation)
// ---------------------------------------------------------------------------
__device__ __align__(1024) float g_gates[2ull * B_DIM * T_DIM * M_DIM + 16384]; // activated gates + scan-prefetch pad
__device__ __align__(1024) float g_xp[(size_t)(T_DIM + 1) * BC];                // padded x (row, b, c)
__device__ __align__(1024) float g_xq[(size_t)(T_DIM + 1) * BC];                // padded reversed x
__device__ __align__(1024) float g_h1p[(size_t)B_DIM * (T_DIM + 1) * 1024];     // layer-1 out padded (b, row, c)
__device__ __align__(1024) float g_h1q[(size_t)B_DIM * (T_DIM + 1) * 1024];     // padded reversed
__device__ __align__(1024) float g_wt1[2ull * 2 * M_DIM * C1];                  // Wt[dir][kk][m][c]
__device__ __align__(1024) float g_wt2[2ull * 2 * M_DIM * 2 * H_DIM];

// ---------------------------------------------------------------------------
__device__ __forceinline__ uint32_t smem_u32(const void* p) {
    uint32_t a;
    asm("{ .reg .u64 t; cvta.to.shared.u64 t, %1; cvt.u32.u64 %0, t; }" : "=r"(a) : "l"(p));
    return a;
}
__device__ __forceinline__ float rna_tf32(float x) {
    float y; asm("cvt.rna.tf32.f32 %0, %1;" : "=f"(y) : "f"(x)); return y;
}
__device__ __forceinline__ void cpa16(uint32_t dst, const void* src) {
    asm volatile("cp.async.cg.shared.global [%0], [%1], 16;" :: "r"(dst), "l"(src));
}
#define CP_COMMIT() asm volatile("cp.async.commit_group;" ::: "memory")
#define CP_WAIT1()  asm volatile("cp.async.wait_group 1;" ::: "memory")

__device__ __forceinline__ void mma_tf32(float c[4], const uint32_t a[4], const uint32_t b[2]) {
    asm volatile("mma.sync.aligned.m16n8k8.row.col.f32.tf32.tf32.f32 "
                 "{%0,%1,%2,%3}, {%4,%5,%6,%7}, {%8,%9}, {%0,%1,%2,%3};"
                 : "+f"(c[0]), "+f"(c[1]), "+f"(c[2]), "+f"(c[3])
                 : "r"(a[0]), "r"(a[1]), "r"(a[2]), "r"(a[3]), "r"(b[0]), "r"(b[1]));
}

__device__ __forceinline__ float sigm(float v) { return 1.f / (1.f + __expf(-v)); }

// ---------------------------------------------------------------------------
// Prepasses
// ---------------------------------------------------------------------------
__global__ void prep_w(const float* __restrict__ W, float* __restrict__ Wt, int CIN)
{
    int o = blockIdx.x * 256 + threadIdx.x;
    int c   = o % CIN;
    int m   = (o / CIN) & 2047;
    int kk  = (o / (CIN * 2048)) & 1;
    int dir = o / (CIN * 4096);
    int g = m >> 9, h = m & 511;
    float v = W[(((size_t)(dir * 4 + g) * 512 + h) * CIN + c) * 2 + kk];
    Wt[o] = rna_tf32(v);
}

__global__ void prep_x(const float* __restrict__ x, float* __restrict__ Xp, float* __restrict__ Xq)
{
    int idx = blockIdx.x * 256 + threadIdx.x;
    int r = idx & (BC - 1);
    int t = idx >> 14;
    float v = rna_tf32(x[idx]);
    Xp[(size_t)(t + 1) * BC + r] = v;
    Xq[(size_t)(T_DIM - t) * BC + r] = v;
}

__global__ void zero_pads(float* Xp, float* Xq, float* h1p, float* h1q)
{
    int idx = blockIdx.x * 256 + threadIdx.x;
    if (idx < BC) { Xp[idx] = 0.f; Xq[idx] = 0.f; }
    int b = idx >> 10, c = idx & 1023;
    h1p[(size_t)b * (T_DIM + 1) * 1024 + c] = 0.f;
    h1q[(size_t)b * (T_DIM + 1) * 1024 + c] = 0.f;
}

// ---------------------------------------------------------------------------
// tf32 mma.sync GEMM + fused activation epilogue.
//   D[m][t] = bias[m] + sum_{kk,c} Wt[dir][kk][m][c] * Xd[t0+kk+t_loc][c]
//   gate = blockIdx.y>>2 : 0 -> tanh, else sigmoid; store G[dir][b][t][m]
// ---------------------------------------------------------------------------
__global__ __launch_bounds__(256, 2)
void qrnn_gemm_mma(const float* __restrict__ X0, const float* __restrict__ X1,
                   const float* __restrict__ Wt, const float* __restrict__ bias,
                   float* __restrict__ G, int CIN, int t_stride, int b_stride)
{
    extern __shared__ float sm[];                 // 3 stages * 8192 floats (96 KB)
    const int tid  = threadIdx.x;
    const int wid  = tid >> 5, lane = tid & 31;
    const int lm   = lane >> 2, lk = lane & 3;
    const int mo   = (wid & 3) * 32;              // warp m-offset in tile
    const int no   = (wid >> 2) * 64;             // warp n-offset in tile
    const int m0   = blockIdx.x * 128;
    const int bcol = blockIdx.y;
    const int b    = bcol >> 2, t0 = (bcol & 3) * 128;
    const int dir  = blockIdx.z;
    const int gate = blockIdx.x >> 2;
    const float* Xd = dir ? X1 : X0;
    const int CPK = CIN >> 5, NCH = CPK * 2;

    const uint32_t sbase = smem_u32(sm);
    const int row = tid >> 3, blk = tid & 7;      // loader coords (x4 along rows)

    float acc[2][8][4];
    #pragma unroll
    for (int i = 0; i < 2; i++)
        #pragma unroll
        for (int j = 0; j < 8; j++)
            #pragma unroll
            for (int k = 0; k < 4; k++) acc[i][j][k] = 0.f;

    // --- async chunk loader: stage s gets A[128x32] + B[128x32], XOR-swizzled
    auto issue = [&](int ic, int s) {
        const int kk = (ic >= CPK) ? 1 : 0;
        const int c0 = (kk ? ic - CPK : ic) << 5;
        const float* Ab = Wt + (size_t)((dir * 2 + kk) * 2048 + m0) * CIN + c0;
        const float* Bb = Xd + (size_t)(t0 + kk) * t_stride + (size_t)b * b_stride + c0;
        const uint32_t st = sbase + s * 32768;
        #pragma unroll
        for (int k = 0; k < 4; k++) {
            int r = row + 32 * k;
            uint32_t off = (uint32_t)r * 128 + ((uint32_t)(blk ^ (r & 7)) << 4);
            cpa16(st + off,         Ab + (size_t)r * CIN + blk * 4);
            cpa16(st + 16384 + off, Bb + (size_t)r * t_stride + blk * 4);
        }
    };

    issue(0, 0); CP_COMMIT();
    issue(1, 1); CP_COMMIT();

    for (int ic = 0; ic < NCH; ic++) {
        const int s = ic % 3;
        CP_WAIT1();
        __syncthreads();

        const uint32_t* As = (const uint32_t*)sm + (size_t)s * 8192;
        const uint32_t* Bs = As + 4096;
        #pragma unroll
        for (int ks = 0; ks < 4; ks++) {
            const int s0 = (((2 * ks)     ^ lm) << 2) + lk;
            const int s1 = (((2 * ks + 1) ^ lm) << 2) + lk;
            uint32_t a[2][4];
            #pragma unroll
            for (int mf = 0; mf < 2; mf++) {
                const uint32_t* p = As + (mo + mf * 16 + lm) * 32;
                a[mf][0] = p[s0]; a[mf][1] = p[256 + s0];
                a[mf][2] = p[s1]; a[mf][3] = p[256 + s1];
            }
            uint32_t bf[8][2];
            #pragma unroll
            for (int nf = 0; nf < 8; nf++) {
                const uint32_t* p = Bs + (no + nf * 8 + lm) * 32;
                bf[nf][0] = p[s0]; bf[nf][1] = p[s1];
            }
            #pragma unroll
            for (int mf = 0; mf < 2; mf++)
                #pragma unroll
                for (int nf = 0; nf < 8; nf++)
                    mma_tf32(acc[mf][nf], a[mf], bf[nf]);
        }

        const int nx = ic + 2;
        if (nx < NCH) issue(nx, nx % 3);
        CP_COMMIT();
    }

    // --- epilogue: bias + activation, store to G[dir][b][t][m]
    const float* bb = bias + dir * 2048 + m0;
    float* Gbase = G + ((size_t)(dir * B_DIM + b) * T_DIM + t0) * M_DIM + m0;
    #pragma unroll
    for (int mf = 0; mf < 2; mf++) {
        const int mr = mo + mf * 16 + lm;
        const float blo = bb[mr], bhi = bb[mr + 8];
        #pragma unroll
        for (int nf = 0; nf < 8; nf++) {
            const int t = no + nf * 8 + 2 * lk;
            float* p = Gbase + (size_t)t * M_DIM + mr;
            float v0 = acc[mf][nf][0] + blo;
            float v1 = acc[mf][nf][1] + blo;
            float v2 = acc[mf][nf][2] + bhi;
            float v3 = acc[mf][nf][3] + bhi;
            if (gate == 0) {
                v0 = 2.f * sigm(2.f * v0) - 1.f;  v1 = 2.f * sigm(2.f * v1) - 1.f;
                v2 = 2.f * sigm(2.f * v2) - 1.f;  v3 = 2.f * sigm(2.f * v3) - 1.f;
            } else {
                v0 = sigm(v0); v1 = sigm(v1); v2 = sigm(v2); v3 = sigm(v3);
            }
            p[0]         = v0;  p[M_DIM]     = v1;
            p[8]         = v2;  p[M_DIM + 8] = v3;
        }
    }
}

// ---------------------------------------------------------------------------
// Recurrence scan over activated gates, depth-4 register prefetch.
//   mode 0: write h1p + h1q (padded, reversed), tf32-rounded; hn raw
//   mode 1: write final output (T,B,2H); hn raw
// ---------------------------------------------------------------------------
__global__ void qrnn_scan3(const float* __restrict__ G, float* __restrict__ o1,
                           float* __restrict__ o2, float* __restrict__ hn, int mode)
{
    const int h   = blockIdx.x * 128 + threadIdx.x;   // 0..511
    const int b   = blockIdx.y;
    const int dir = blockIdx.z;
    const float* Gd = G + (size_t)(dir * B_DIM + b) * T_DIM * M_DIM + h;
    const int co = dir * 512 + h;

    float4 q[4];
    #pragma unroll
    for (int d = 0; d < 4; d++) {
        const float* p = Gd + (size_t)d * M_DIM;
        q[d] = make_float4(p[0], p[512], p[1024], p[1536]);
    }
    float c = 0.f;
    #pragma unroll 4
    for (int t = 0; t < T_DIM; t++) {
        const float* p = Gd + (size_t)(t + 4) * M_DIM;   // padded buffer: unconditional
        float4 nv = make_float4(p[0], p[512], p[1024], p[1536]);
        float4 cur = q[t & 3];
        c = fmaf(cur.y, c, cur.w * cur.x);               // c = f*c + i*z
        float val = cur.z * c;                           // o*c
        if (mode == 0) {
            float rv = rna_tf32(val);
            o1[((size_t)b * (T_DIM + 1) + 1 + t) * 1024 + co] = rv;
            o2[((size_t)b * (T_DIM + 1) + (T_DIM - t)) * 1024 + co] = rv;
        } else {
            o1[((size_t)t * B_DIM + b) * 1024 + co] = val;
        }
        if ((dir == 0 && t == T_DIM - 2) || (dir == 1 && t == 0))
            hn[(size_t)b * 1024 + co] = val;
        q[t & 3] = nv;
    }
}

// ---------------------------------------------------------------------------
extern "C" void kernel_launch(void* const* d_in, const int* in_sizes, int n_in,
                              void* d_out, int out_size)
{
    const float* x  = (const float*)d_in[0];
    const float* w0 = (const float*)d_in[1];
    const float* b0 = (const float*)d_in[2];
    const float* w1 = (const float*)d_in[3];
    const float* b1 = (const float*)d_in[4];
    float* out = (float*)d_out;

    float *gates, *xp, *xq, *h1p, *h1q, *wt1, *wt2;
    cudaGetSymbolAddress((void**)&gates, g_gates);
    cudaGetSymbolAddress((void**)&xp,  g_xp);
    cudaGetSymbolAddress((void**)&xq,  g_xq);
    cudaGetSymbolAddress((void**)&h1p, g_h1p);
    cudaGetSymbolAddress((void**)&h1q, g_h1q);
    cudaGetSymbolAddress((void**)&wt1, g_wt1);
    cudaGetSymbolAddress((void**)&wt2, g_wt2);

    cudaFuncSetAttribute(qrnn_gemm_mma, cudaFuncAttributeMaxDynamicSharedMemorySize, 96 * 1024);

    const size_t OUT_SEQ = (size_t)T_DIM * B_DIM * 2 * H_DIM;
    const size_t HN_L    = (size_t)B_DIM * 2 * H_DIM;

    prep_w<<<(2 * 2 * 2048 * C1) / 256, 256>>>(w0, wt1, C1);
    prep_w<<<(2 * 2 * 2048 * 2 * H_DIM) / 256, 256>>>(w1, wt2, 2 * H_DIM);
    prep_x<<<(T_DIM * BC) / 256, 256>>>(x, xp, xq);
    zero_pads<<<128, 256>>>(xp, xq, h1p, h1q);

    dim3 ggrid(16, 128, 2), gblk(256);
    dim3 sgrid(4, B_DIM, 2), sblk(128);
    const int DSM = 96 * 1024;

    // Layer 1: Xp/Xq (row, b, c): t_stride = BC, b_stride = C1
    qrnn_gemm_mma<<<ggrid, gblk, DSM>>>(xp, xq, wt1, b0, gates, C1, BC, C1);
    qrnn_scan3<<<sgrid, sblk>>>(gates, h1p, h1q, out + OUT_SEQ, 0);

    // Layer 2: h1p/h1q (b, row, c): t_stride = 1024, b_stride = 513*1024
    qrnn_gemm_mma<<<ggrid, gblk, DSM>>>(h1p, h1q, wt2, b1, gates, 2 * H_DIM,
                                        1024, (T_DIM + 1) * 1024);
    qrnn_scan3<<<sgrid, sblk>>>(gates, out, nullptr, out + OUT_SEQ + HN_L, 1);
}

// round 6
// speedup vs baseline: 8.5711x; 1.6972x over previous
#include <cuda_runtime.h>
#include <cuda_fp16.h>
#include <cstdint>
#include <math.h>

#define T_DIM 512
#define B_DIM 32
#define C1    512
#define H_DIM 512
#define M_DIM 2048          // 4 gates * H per direction
#define BC    (B_DIM * C1)  // 16384

// ---------------------------------------------------------------------------
// Scratch (__device__ globals — no runtime allocation)
// ---------------------------------------------------------------------------
__device__ __align__(1024) float  g_gates[2ull * B_DIM * T_DIM * M_DIM + 16384]; // activated gates + scan pad
__device__ __align__(1024) __half g_xp[(size_t)(T_DIM + 1) * BC];                // padded x (row, b, c), fp16
__device__ __align__(1024) __half g_xq[(size_t)(T_DIM + 1) * BC];                // padded reversed x
__device__ __align__(1024) __half g_h1p[(size_t)B_DIM * (T_DIM + 1) * 1024];     // layer-1 out padded (b,row,c)
__device__ __align__(1024) __half g_h1q[(size_t)B_DIM * (T_DIM + 1) * 1024];     // padded reversed
__device__ __align__(1024) __half g_wt1[2ull * 2 * M_DIM * C1];                  // Wt[dir][kk][m][c]
__device__ __align__(1024) __half g_wt2[2ull * 2 * M_DIM * 2 * H_DIM];

// ---------------------------------------------------------------------------
__device__ __forceinline__ uint32_t smem_u32(const void* p) {
    uint32_t a;
    asm("{ .reg .u64 t; cvta.to.shared.u64 t, %1; cvt.u32.u64 %0, t; }" : "=r"(a) : "l"(p));
    return a;
}
__device__ __forceinline__ void cpa16(uint32_t dst, const void* src) {
    asm volatile("cp.async.cg.shared.global [%0], [%1], 16;" :: "r"(dst), "l"(src));
}
#define CP_COMMIT() asm volatile("cp.async.commit_group;" ::: "memory")
#define CP_WAIT1()  asm volatile("cp.async.wait_group 1;" ::: "memory")

__device__ __forceinline__ void ldm_x4(uint32_t r[4], uint32_t addr) {
    asm volatile("ldmatrix.sync.aligned.m8n8.x4.shared.b16 {%0,%1,%2,%3}, [%4];"
                 : "=r"(r[0]), "=r"(r[1]), "=r"(r[2]), "=r"(r[3]) : "r"(addr));
}
__device__ __forceinline__ void mma_f16(float c[4], const uint32_t a[4], uint32_t b0, uint32_t b1) {
    asm volatile("mma.sync.aligned.m16n8k16.row.col.f32.f16.f16.f32 "
                 "{%0,%1,%2,%3}, {%4,%5,%6,%7}, {%8,%9}, {%0,%1,%2,%3};"
                 : "+f"(c[0]), "+f"(c[1]), "+f"(c[2]), "+f"(c[3])
                 : "r"(a[0]), "r"(a[1]), "r"(a[2]), "r"(a[3]), "r"(b0), "r"(b1));
}
__device__ __forceinline__ float sigm(float v) { return 1.f / (1.f + __expf(-v)); }

// ---------------------------------------------------------------------------
// Prepasses: round everything to fp16
// ---------------------------------------------------------------------------
__global__ void prep_w(const float* __restrict__ W, __half* __restrict__ Wt, int CIN)
{
    int o = blockIdx.x * 256 + threadIdx.x;
    int c   = o % CIN;
    int m   = (o / CIN) & 2047;
    int kk  = (o / (CIN * 2048)) & 1;
    int dir = o / (CIN * 4096);
    int g = m >> 9, h = m & 511;
    float v = W[(((size_t)(dir * 4 + g) * 512 + h) * CIN + c) * 2 + kk];
    Wt[o] = __float2half_rn(v);
}

__global__ void prep_x(const float* __restrict__ x, __half* __restrict__ Xp, __half* __restrict__ Xq)
{
    int idx = blockIdx.x * 256 + threadIdx.x;
    int r = idx & (BC - 1);
    int t = idx >> 14;
    __half v = __float2half_rn(x[idx]);
    Xp[(size_t)(t + 1) * BC + r] = v;
    Xq[(size_t)(T_DIM - t) * BC + r] = v;
}

__global__ void zero_pads(__half* Xp, __half* Xq, __half* h1p, __half* h1q)
{
    int idx = blockIdx.x * 256 + threadIdx.x;
    __half z = __float2half_rn(0.f);
    if (idx < BC) { Xp[idx] = z; Xq[idx] = z; }
    int b = idx >> 10, c = idx & 1023;
    h1p[(size_t)b * (T_DIM + 1) * 1024 + c] = z;
    h1q[(size_t)b * (T_DIM + 1) * 1024 + c] = z;
}

// ---------------------------------------------------------------------------
// fp16 mma.sync m16n8k16 GEMM + fused activation epilogue.
//   D[m][t] = bias[m] + sum_{kk,c} Wt[dir][kk][m][c] * Xd[t0+kk+t_loc][c]
//   gate = blockIdx.x>>2 : 0 -> tanh, else sigmoid; store G[dir][b][t][m]
// SMEM stage = A[128m x 32k] (8KB) + B[128t x 32k] (8KB), XOR-swizzled granules.
// B fragments use NON-trans ldmatrix: SMEM B is [t][k] (k-contiguous), which
// with rows=n, cols=k gives exactly the mma B layout (k-pair at n=l/4).
// ---------------------------------------------------------------------------
__global__ __launch_bounds__(256, 2)
void qrnn_gemm_mma(const __half* __restrict__ X0, const __half* __restrict__ X1,
                   const __half* __restrict__ Wt, const float* __restrict__ bias,
                   float* __restrict__ G, int CIN, int t_stride, int b_stride)
{
    extern __shared__ __align__(128) char dsm[];   // 3 stages * 16 KB
    const int tid  = threadIdx.x;
    const int wid  = tid >> 5, lane = tid & 31;
    const int lm   = lane >> 2, lk = lane & 3;
    const int mo   = (wid & 3) * 32;               // warp m-offset
    const int no   = (wid >> 2) * 64;              // warp n(t)-offset
    const int m0   = blockIdx.x * 128;
    const int bcol = blockIdx.y;
    const int b    = bcol >> 2, t0 = (bcol & 3) * 128;
    const int dir  = blockIdx.z;
    const int gate = blockIdx.x >> 2;
    const __half* Xd = dir ? X1 : X0;
    const int CPK = CIN >> 5, NCH = CPK * 2;

    const uint32_t sbase = smem_u32(dsm);

    float acc[2][8][4];
    #pragma unroll
    for (int i = 0; i < 2; i++)
        #pragma unroll
        for (int j = 0; j < 8; j++)
            #pragma unroll
            for (int k = 0; k < 4; k++) acc[i][j][k] = 0.f;

    // --- async chunk loader (granule = 16B = 8 halves; swizzle g ^= (row>>1)&3)
    auto issue = [&](int ic, int s) {
        const int kk = (ic >= CPK) ? 1 : 0;
        const int c0 = (kk ? ic - CPK : ic) << 5;
        const __half* Ab = Wt + (size_t)((dir * 2 + kk) * 2048 + m0) * CIN + c0;
        const __half* Bb = Xd + (size_t)(t0 + kk) * t_stride + (size_t)b * b_stride + c0;
        const uint32_t st = sbase + s * 16384;
        #pragma unroll
        for (int p = 0; p < 2; p++) {
            int gid = p * 256 + tid;               // 0..511 granules
            int r = gid >> 2, g = gid & 3;
            uint32_t off = (uint32_t)r * 64 + (uint32_t)((g ^ ((r >> 1) & 3)) << 4);
            cpa16(st + off,        Ab + (size_t)r * CIN + g * 8);
            cpa16(st + 8192 + off, Bb + (size_t)r * t_stride + g * 8);
        }
    };

    issue(0, 0); CP_COMMIT();
    issue(1, 1); CP_COMMIT();

    const int lq = lane >> 3, lr = lane & 7;       // ldmatrix quadrant / row-in-quadrant

    for (int ic = 0; ic < NCH; ic++) {
        const int s = ic % 3;
        CP_WAIT1();
        __syncthreads();

        const uint32_t As = sbase + s * 16384;
        const uint32_t Bs = As + 8192;
        #pragma unroll
        for (int ks = 0; ks < 2; ks++) {
            // A fragments: 2 m-blocks of 16 rows, k16 at granules (2ks, 2ks+1)
            // x4 matrices: m0=(rows0-7,k-lo) m1=(rows8-15,k-lo) m2=(rows0-7,k-hi) m3=(rows8-15,k-hi)
            uint32_t a[2][4];
            #pragma unroll
            for (int mf = 0; mf < 2; mf++) {
                int R = mo + mf * 16 + lr + ((lq & 1) << 3);
                int g = ks * 2 + (lq >> 1);
                ldm_x4(a[mf], As + (uint32_t)R * 64 + (uint32_t)((g ^ ((R >> 1) & 3)) << 4));
            }
            // B fragments (NON-trans): 4 n-blocks of 16 rows
            // x4 matrices: m0=(n0-7,k-lo) m1=(n0-7,k-hi) m2=(n8-15,k-lo) m3=(n8-15,k-hi)
            // regs: [0]=b0 nblk0, [1]=b1 nblk0, [2]=b0 nblk1, [3]=b1 nblk1
            uint32_t bf[4][4];
            #pragma unroll
            for (int nb = 0; nb < 4; nb++) {
                int R = no + nb * 16 + lr + ((lq >> 1) << 3);
                int g = ks * 2 + (lq & 1);
                ldm_x4(bf[nb], Bs + (uint32_t)R * 64 + (uint32_t)((g ^ ((R >> 1) & 3)) << 4));
            }
            #pragma unroll
            for (int mf = 0; mf < 2; mf++)
                #pragma unroll
                for (int nf = 0; nf < 8; nf++)
                    mma_f16(acc[mf][nf], a[mf], bf[nf >> 1][(nf & 1) * 2], bf[nf >> 1][(nf & 1) * 2 + 1]);
        }

        const int nx = ic + 2;
        if (nx < NCH) issue(nx, nx % 3);
        CP_COMMIT();
    }

    // --- epilogue: bias + activation, store to G[dir][b][t][m]
    const float* bb = bias + dir * 2048 + m0;
    float* Gbase = G + ((size_t)(dir * B_DIM + b) * T_DIM + t0) * M_DIM + m0;
    #pragma unroll
    for (int mf = 0; mf < 2; mf++) {
        const int mr = mo + mf * 16 + lm;
        const float blo = bb[mr], bhi = bb[mr + 8];
        #pragma unroll
        for (int nf = 0; nf < 8; nf++) {
            const int t = no + nf * 8 + 2 * lk;
            float* p = Gbase + (size_t)t * M_DIM + mr;
            float v0 = acc[mf][nf][0] + blo;
            float v1 = acc[mf][nf][1] + blo;
            float v2 = acc[mf][nf][2] + bhi;
            float v3 = acc[mf][nf][3] + bhi;
            if (gate == 0) {
                v0 = 2.f * sigm(2.f * v0) - 1.f;  v1 = 2.f * sigm(2.f * v1) - 1.f;
                v2 = 2.f * sigm(2.f * v2) - 1.f;  v3 = 2.f * sigm(2.f * v3) - 1.f;
            } else {
                v0 = sigm(v0); v1 = sigm(v1); v2 = sigm(v2); v3 = sigm(v3);
            }
            p[0] = v0;  p[M_DIM]     = v1;
            p[8] = v2;  p[M_DIM + 8] = v3;
        }
    }
}

// ---------------------------------------------------------------------------
// Recurrence scan over activated gates, depth-4 register prefetch.
//   mode 0: write h1p + h1q (padded, reversed) as fp16; hn raw fp32
//   mode 1: write final output (T,B,2H) fp32; hn raw fp32
// ---------------------------------------------------------------------------
__global__ void qrnn_scan3(const float* __restrict__ G, float* __restrict__ o1f,
                           __half* __restrict__ o1h, __half* __restrict__ o2h,
                           float* __restrict__ hn, int mode)
{
    const int h   = blockIdx.x * 128 + threadIdx.x;
    const int b   = blockIdx.y;
    const int dir = blockIdx.z;
    const float* Gd = G + (size_t)(dir * B_DIM + b) * T_DIM * M_DIM + h;
    const int co = dir * 512 + h;

    float4 q[4];
    #pragma unroll
    for (int d = 0; d < 4; d++) {
        const float* p = Gd + (size_t)d * M_DIM;
        q[d] = make_float4(p[0], p[512], p[1024], p[1536]);
    }
    float c = 0.f;
    #pragma unroll 4
    for (int t = 0; t < T_DIM; t++) {
        const float* p = Gd + (size_t)(t + 4) * M_DIM;
        float4 nv = make_float4(p[0], p[512], p[1024], p[1536]);
        float4 cur = q[t & 3];
        c = fmaf(cur.y, c, cur.w * cur.x);   // c = f*c + i*z
        float val = cur.z * c;               // o*c
        if (mode == 0) {
            __half rv = __float2half_rn(val);
            o1h[((size_t)b * (T_DIM + 1) + 1 + t) * 1024 + co] = rv;
            o2h[((size_t)b * (T_DIM + 1) + (T_DIM - t)) * 1024 + co] = rv;
        } else {
            o1f[((size_t)t * B_DIM + b) * 1024 + co] = val;
        }
        if ((dir == 0 && t == T_DIM - 2) || (dir == 1 && t == 0))
            hn[(size_t)b * 1024 + co] = val;
        q[t & 3] = nv;
    }
}

// ---------------------------------------------------------------------------
extern "C" void kernel_launch(void* const* d_in, const int* in_sizes, int n_in,
                              void* d_out, int out_size)
{
    const float* x  = (const float*)d_in[0];
    const float* w0 = (const float*)d_in[1];
    const float* b0 = (const float*)d_in[2];
    const float* w1 = (const float*)d_in[3];
    const float* b1 = (const float*)d_in[4];
    float* out = (float*)d_out;

    float *gates;  __half *xp, *xq, *h1p, *h1q, *wt1, *wt2;
    cudaGetSymbolAddress((void**)&gates, g_gates);
    cudaGetSymbolAddress((void**)&xp,  g_xp);
    cudaGetSymbolAddress((void**)&xq,  g_xq);
    cudaGetSymbolAddress((void**)&h1p, g_h1p);
    cudaGetSymbolAddress((void**)&h1q, g_h1q);
    cudaGetSymbolAddress((void**)&wt1, g_wt1);
    cudaGetSymbolAddress((void**)&wt2, g_wt2);

    cudaFuncSetAttribute(qrnn_gemm_mma, cudaFuncAttributeMaxDynamicSharedMemorySize, 48 * 1024);

    const size_t OUT_SEQ = (size_t)T_DIM * B_DIM * 2 * H_DIM;
    const size_t HN_L    = (size_t)B_DIM * 2 * H_DIM;

    prep_w<<<(2 * 2 * 2048 * C1) / 256, 256>>>(w0, wt1, C1);
    prep_w<<<(2 * 2 * 2048 * 2 * H_DIM) / 256, 256>>>(w1, wt2, 2 * H_DIM);
    prep_x<<<(T_DIM * BC) / 256, 256>>>(x, xp, xq);
    zero_pads<<<128, 256>>>(xp, xq, h1p, h1q);

    dim3 ggrid(16, 128, 2), gblk(256);
    dim3 sgrid(4, B_DIM, 2), sblk(128);
    const int DSM = 48 * 1024;

    // Layer 1: Xp/Xq (row, b, c): t_stride = BC, b_stride = C1
    qrnn_gemm_mma<<<ggrid, gblk, DSM>>>(xp, xq, wt1, b0, gates, C1, BC, C1);
    qrnn_scan3<<<sgrid, sblk>>>(gates, nullptr, h1p, h1q, out + OUT_SEQ, 0);

    // Layer 2: h1p/h1q (b, row, c): t_stride = 1024, b_stride = 513*1024
    qrnn_gemm_mma<<<ggrid, gblk, DSM>>>(h1p, h1q, wt2, b1, gates, 2 * H_DIM,
                                        1024, (T_DIM + 1) * 1024);
    qrnn_scan3<<<sgrid, sblk>>>(gates, out, nullptr, nullptr, out + OUT_SEQ + HN_L, 1);
}

// round 7
// speedup vs baseline: 8.6538x; 1.0097x over previous
#include <cuda_runtime.h>
#include <cuda_fp16.h>
#include <cstdint>
#include <math.h>

#define T_DIM 512
#define B_DIM 32
#define C1    512
#define H_DIM 512
#define M_DIM 2048          // 4 gates * H per direction
#define BC    (B_DIM * C1)  // 16384
#define NCHK  8
#define CHK   64            // T / NCHK

// ---------------------------------------------------------------------------
// Scratch (__device__ globals — no runtime allocation)
// ---------------------------------------------------------------------------
__device__ __align__(1024) __half g_gates[2ull * B_DIM * T_DIM * M_DIM];      // activated gates fp16 (134MB)
__device__ __align__(1024) __half g_xp[(size_t)(T_DIM + 2) * BC];             // padded x: rows 0..513, row 1+t = x[t]
__device__ __align__(1024) __half g_h1p[(size_t)B_DIM * (T_DIM + 2) * 1024];  // layer-1 out, same padding
__device__ __align__(1024) __half g_wt1[2ull * 2 * M_DIM * C1];               // Wt[dir][kk][m][c]
__device__ __align__(1024) __half g_wt2[2ull * 2 * M_DIM * 2 * H_DIM];
__device__ float g_sumA[2 * B_DIM * NCHK * 512];                               // chunk decay
__device__ float g_sumB[2 * B_DIM * NCHK * 512];                               // chunk offset
__device__ float g_cst [2 * B_DIM * NCHK * 512];                               // chunk entry state

// ---------------------------------------------------------------------------
__device__ __forceinline__ uint32_t smem_u32(const void* p) {
    uint32_t a;
    asm("{ .reg .u64 t; cvta.to.shared.u64 t, %1; cvt.u32.u64 %0, t; }" : "=r"(a) : "l"(p));
    return a;
}
__device__ __forceinline__ void cpa16(uint32_t dst, const void* src) {
    asm volatile("cp.async.cg.shared.global [%0], [%1], 16;" :: "r"(dst), "l"(src));
}
#define CP_COMMIT() asm volatile("cp.async.commit_group;" ::: "memory")
#define CP_WAIT1()  asm volatile("cp.async.wait_group 1;" ::: "memory")

__device__ __forceinline__ void ldm_x4(uint32_t r[4], uint32_t addr) {
    asm volatile("ldmatrix.sync.aligned.m8n8.x4.shared.b16 {%0,%1,%2,%3}, [%4];"
                 : "=r"(r[0]), "=r"(r[1]), "=r"(r[2]), "=r"(r[3]) : "r"(addr));
}
__device__ __forceinline__ void mma_f16(float c[4], const uint32_t a[4], uint32_t b0, uint32_t b1) {
    asm volatile("mma.sync.aligned.m16n8k16.row.col.f32.f16.f16.f32 "
                 "{%0,%1,%2,%3}, {%4,%5,%6,%7}, {%8,%9}, {%0,%1,%2,%3};"
                 : "+f"(c[0]), "+f"(c[1]), "+f"(c[2]), "+f"(c[3])
                 : "r"(a[0]), "r"(a[1]), "r"(a[2]), "r"(a[3]), "r"(b0), "r"(b1));
}
__device__ __forceinline__ float sigm(float v) { return 1.f / (1.f + __expf(-v)); }

// ---------------------------------------------------------------------------
// Prepasses
// ---------------------------------------------------------------------------
__global__ void prep_w(const float* __restrict__ W, __half* __restrict__ Wt, int CIN)
{
    int o = blockIdx.x * 256 + threadIdx.x;
    int c   = o % CIN;
    int m   = (o / CIN) & 2047;
    int kk  = (o / (CIN * 2048)) & 1;
    int dir = o / (CIN * 4096);
    int g = m >> 9, h = m & 511;
    Wt[o] = __float2half_rn(W[(((size_t)(dir * 4 + g) * 512 + h) * CIN + c) * 2 + kk]);
}

__global__ void prep_x(const float* __restrict__ x, __half* __restrict__ Xp)
{
    int idx = blockIdx.x * 256 + threadIdx.x;    // < T*BC
    int r = idx & (BC - 1);
    int t = idx >> 14;
    Xp[(size_t)(t + 1) * BC + r] = __float2half_rn(x[idx]);
}

__global__ void zero_pads(__half* Xp, __half* h1p)
{
    int idx = blockIdx.x * 256 + threadIdx.x;    // < 32768
    __half z = __float2half_rn(0.f);
    if (idx < BC) {
        Xp[idx] = z;
        Xp[(size_t)(T_DIM + 1) * BC + idx] = z;
    }
    int b = idx >> 10, c = idx & 1023;
    h1p[(size_t)b * (T_DIM + 2) * 1024 + c] = z;
    h1p[((size_t)b * (T_DIM + 2) + T_DIM + 1) * 1024 + c] = z;
}

// ---------------------------------------------------------------------------
// fp16 mma.sync m16n8k16 GEMM + fused activation epilogue.
// dir=1 reads the SAME padded buffer with negative row stride:
//   row = 513 - t0 - kk - r  (zero rows at 0 and 513 supply the conv pad)
// ---------------------------------------------------------------------------
__global__ __launch_bounds__(256, 2)
void qrnn_gemm_mma(const __half* __restrict__ X,
                   const __half* __restrict__ Wt, const float* __restrict__ bias,
                   __half* __restrict__ G, int CIN, int row_stride, int b_stride)
{
    extern __shared__ __align__(128) char dsm[];   // 3 stages * 16 KB
    const int tid  = threadIdx.x;
    const int wid  = tid >> 5, lane = tid & 31;
    const int lm   = lane >> 2, lk = lane & 3;
    const int mo   = (wid & 3) * 32;
    const int no   = (wid >> 2) * 64;
    const int m0   = blockIdx.x * 128;
    const int bcol = blockIdx.y;
    const int b    = bcol >> 2, t0 = (bcol & 3) * 128;
    const int dir  = blockIdx.z;
    const int gate = blockIdx.x >> 2;
    const int CPK = CIN >> 5, NCH = CPK * 2;

    const uint32_t sbase = smem_u32(dsm);

    float acc[2][8][4];
    #pragma unroll
    for (int i = 0; i < 2; i++)
        #pragma unroll
        for (int j = 0; j < 8; j++)
            #pragma unroll
            for (int k = 0; k < 4; k++) acc[i][j][k] = 0.f;

    auto issue = [&](int ic, int s) {
        const int kk = (ic >= CPK) ? 1 : 0;
        const int c0 = (kk ? ic - CPK : ic) << 5;
        const __half* Ab = Wt + (size_t)((dir * 2 + kk) * 2048 + m0) * CIN + c0;
        const __half* Bb;
        ptrdiff_t rst;
        if (dir == 0) {
            Bb  = X + (size_t)b * b_stride + (size_t)(t0 + kk) * row_stride + c0;
            rst = row_stride;
        } else {
            Bb  = X + (size_t)b * b_stride + (size_t)(T_DIM + 1 - t0 - kk) * row_stride + c0;
            rst = -(ptrdiff_t)row_stride;
        }
        const uint32_t st = sbase + s * 16384;
        #pragma unroll
        for (int p = 0; p < 2; p++) {
            int gid = p * 256 + tid;               // 0..511 granules
            int r = gid >> 2, g = gid & 3;
            uint32_t off = (uint32_t)r * 64 + (uint32_t)((g ^ ((r >> 1) & 3)) << 4);
            cpa16(st + off,        Ab + (size_t)r * CIN + g * 8);
            cpa16(st + 8192 + off, Bb + (ptrdiff_t)r * rst + g * 8);
        }
    };

    issue(0, 0); CP_COMMIT();
    issue(1, 1); CP_COMMIT();

    const int lq = lane >> 3, lr = lane & 7;

    for (int ic = 0; ic < NCH; ic++) {
        const int s = ic % 3;
        CP_WAIT1();
        __syncthreads();

        const uint32_t As = sbase + s * 16384;
        const uint32_t Bs = As + 8192;
        #pragma unroll
        for (int ks = 0; ks < 2; ks++) {
            uint32_t a[2][4];
            #pragma unroll
            for (int mf = 0; mf < 2; mf++) {
                int R = mo + mf * 16 + lr + ((lq & 1) << 3);
                int g = ks * 2 + (lq >> 1);
                ldm_x4(a[mf], As + (uint32_t)R * 64 + (uint32_t)((g ^ ((R >> 1) & 3)) << 4));
            }
            uint32_t bf[4][4];
            #pragma unroll
            for (int nb = 0; nb < 4; nb++) {
                int R = no + nb * 16 + lr + ((lq >> 1) << 3);
                int g = ks * 2 + (lq & 1);
                ldm_x4(bf[nb], Bs + (uint32_t)R * 64 + (uint32_t)((g ^ ((R >> 1) & 3)) << 4));
            }
            #pragma unroll
            for (int mf = 0; mf < 2; mf++)
                #pragma unroll
                for (int nf = 0; nf < 8; nf++)
                    mma_f16(acc[mf][nf], a[mf], bf[nf >> 1][(nf & 1) * 2], bf[nf >> 1][(nf & 1) * 2 + 1]);
        }

        const int nx = ic + 2;
        if (nx < NCH) issue(nx, nx % 3);
        CP_COMMIT();
    }

    // epilogue: bias + activation, store fp16 gates to G[dir][b][t][m]
    const float* bb = bias + dir * 2048 + m0;
    __half* Gbase = G + ((size_t)(dir * B_DIM + b) * T_DIM + t0) * M_DIM + m0;
    #pragma unroll
    for (int mf = 0; mf < 2; mf++) {
        const int mr = mo + mf * 16 + lm;
        const float blo = bb[mr], bhi = bb[mr + 8];
        #pragma unroll
        for (int nf = 0; nf < 8; nf++) {
            const int t = no + nf * 8 + 2 * lk;
            __half* p = Gbase + (size_t)t * M_DIM + mr;
            float v0 = acc[mf][nf][0] + blo;
            float v1 = acc[mf][nf][1] + blo;
            float v2 = acc[mf][nf][2] + bhi;
            float v3 = acc[mf][nf][3] + bhi;
            if (gate == 0) {
                v0 = 2.f * sigm(2.f * v0) - 1.f;  v1 = 2.f * sigm(2.f * v1) - 1.f;
                v2 = 2.f * sigm(2.f * v2) - 1.f;  v3 = 2.f * sigm(2.f * v3) - 1.f;
            } else {
                v0 = sigm(v0); v1 = sigm(v1); v2 = sigm(v2); v3 = sigm(v3);
            }
            p[0] = __float2half_rn(v0);  p[M_DIM]     = __float2half_rn(v1);
            p[8] = __float2half_rn(v2);  p[M_DIM + 8] = __float2half_rn(v3);
        }
    }
}

// ---------------------------------------------------------------------------
// Chunk-parallel scan.
//   Phase A: per (dir,b,chunk,h): decay A = prod f, offset B = scan(c=0)
//   Phase B: per (dir,b,h): combine 8 chunk summaries -> c_start per chunk
//   Phase C: rescan chunk from c_start, write outputs + hn
// ---------------------------------------------------------------------------
__global__ void scan_a(const __half* __restrict__ G,
                       float* __restrict__ sA, float* __restrict__ sB)
{
    const int h = blockIdx.x * 128 + threadIdx.x;
    const int b = blockIdx.y;
    const int dir = blockIdx.z >> 3, ch = blockIdx.z & 7;
    const __half* Gd = G + ((size_t)(dir * B_DIM + b) * T_DIM + ch * CHK) * M_DIM + h;

    float a = 1.f, c = 0.f;
    #pragma unroll 4
    for (int t = 0; t < CHK; t++) {
        const __half* p = Gd + (size_t)t * M_DIM;
        float z = __half2float(p[0]);
        float f = __half2float(p[512]);
        float i = __half2float(p[1536]);
        a *= f;
        c = fmaf(f, c, i * z);
    }
    int o = (((dir * B_DIM + b) * NCHK) + ch) * 512 + h;
    sA[o] = a; sB[o] = c;
}

__global__ void scan_b(const float* __restrict__ sA, const float* __restrict__ sB,
                       float* __restrict__ cs)
{
    int idx = blockIdx.x * 256 + threadIdx.x;       // (dir*B+b)*512 + h, < 32768
    int lane = idx >> 9, h = idx & 511;
    float c = 0.f;
    #pragma unroll
    for (int j = 0; j < NCHK; j++) {
        int o = (lane * NCHK + j) * 512 + h;
        cs[o] = c;
        c = fmaf(sA[o], c, sB[o]);
    }
}

__global__ void scan_c(const __half* __restrict__ G, const float* __restrict__ cs,
                       float* __restrict__ o1f, __half* __restrict__ o1h,
                       float* __restrict__ hn, int mode)
{
    const int h = blockIdx.x * 128 + threadIdx.x;
    const int b = blockIdx.y;
    const int dir = blockIdx.z >> 3, ch = blockIdx.z & 7;
    const __half* Gd = G + ((size_t)(dir * B_DIM + b) * T_DIM + ch * CHK) * M_DIM + h;
    const int co = dir * 512 + h;

    float c = cs[(((dir * B_DIM + b) * NCHK) + ch) * 512 + h];
    #pragma unroll 4
    for (int t = 0; t < CHK; t++) {
        const __half* p = Gd + (size_t)t * M_DIM;
        float z  = __half2float(p[0]);
        float f  = __half2float(p[512]);
        float og = __half2float(p[1024]);
        float i  = __half2float(p[1536]);
        c = fmaf(f, c, i * z);
        float val = og * c;
        int gt = ch * CHK + t;
        if (mode == 0) {
            o1h[((size_t)b * (T_DIM + 2) + 1 + gt) * 1024 + co] = __float2half_rn(val);
        } else {
            o1f[((size_t)gt * B_DIM + b) * 1024 + co] = val;
        }
        if ((dir == 0 && gt == T_DIM - 2) || (dir == 1 && gt == 0))
            hn[(size_t)b * 1024 + co] = val;
    }
}

// ---------------------------------------------------------------------------
extern "C" void kernel_launch(void* const* d_in, const int* in_sizes, int n_in,
                              void* d_out, int out_size)
{
    const float* x  = (const float*)d_in[0];
    const float* w0 = (const float*)d_in[1];
    const float* b0 = (const float*)d_in[2];
    const float* w1 = (const float*)d_in[3];
    const float* b1 = (const float*)d_in[4];
    float* out = (float*)d_out;

    __half *gates, *xp, *h1p, *wt1, *wt2;
    float *sA, *sB, *cst;
    cudaGetSymbolAddress((void**)&gates, g_gates);
    cudaGetSymbolAddress((void**)&xp,  g_xp);
    cudaGetSymbolAddress((void**)&h1p, g_h1p);
    cudaGetSymbolAddress((void**)&wt1, g_wt1);
    cudaGetSymbolAddress((void**)&wt2, g_wt2);
    cudaGetSymbolAddress((void**)&sA,  g_sumA);
    cudaGetSymbolAddress((void**)&sB,  g_sumB);
    cudaGetSymbolAddress((void**)&cst, g_cst);

    cudaFuncSetAttribute(qrnn_gemm_mma, cudaFuncAttributeMaxDynamicSharedMemorySize, 48 * 1024);

    const size_t OUT_SEQ = (size_t)T_DIM * B_DIM * 2 * H_DIM;
    const size_t HN_L    = (size_t)B_DIM * 2 * H_DIM;

    prep_w<<<(2 * 2 * 2048 * C1) / 256, 256>>>(w0, wt1, C1);
    prep_w<<<(2 * 2 * 2048 * 2 * H_DIM) / 256, 256>>>(w1, wt2, 2 * H_DIM);
    prep_x<<<(T_DIM * BC) / 256, 256>>>(x, xp);
    zero_pads<<<128, 256>>>(xp, h1p);

    dim3 ggrid(16, 128, 2), gblk(256);
    dim3 scgrid(4, B_DIM, 16), scblk(128);
    const int DSM = 48 * 1024;

    // Layer 1: xp (row, b, c): row_stride = BC, b_stride = C1
    qrnn_gemm_mma<<<ggrid, gblk, DSM>>>(xp, wt1, b0, gates, C1, BC, C1);
    scan_a<<<scgrid, scblk>>>(gates, sA, sB);
    scan_b<<<128, 256>>>(sA, sB, cst);
    scan_c<<<scgrid, scblk>>>(gates, cst, nullptr, h1p, out + OUT_SEQ, 0);

    // Layer 2: h1p (b, row, c): row_stride = 1024, b_stride = 514*1024
    qrnn_gemm_mma<<<ggrid, gblk, DSM>>>(h1p, wt2, b1, gates, 2 * H_DIM,
                                        1024, (T_DIM + 2) * 1024);
    scan_a<<<scgrid, scblk>>>(gates, sA, sB);
    scan_b<<<128, 256>>>(sA, sB, cst);
    scan_c<<<scgrid, scblk>>>(gates, cst, out, nullptr, out + OUT_SEQ + HN_L, 1);
}